// round 2
// baseline (speedup 1.0000x reference)
#include <cuda_runtime.h>
#include <cuda_bf16.h>
#include <cstdint>

// Problem constants (from reference)
#define N_NODES 100000
#define N_EDGES 3200000
#define IN_F    256
#define OUT_F   128
#define NEG_SLOPE 0.2f

// Scratch: support = lrelu(F @ W^T), [N_NODES, OUT_F] fp32 (51.2 MB)
__device__ float g_support[(size_t)N_NODES * OUT_F];

// ---------------------------------------------------------------------------
// Kernel 1: tiled fp32 GEMM + LeakyReLU
//   C[m][n] = lrelu( sum_k F[m][k] * W[n][k] ),  m < N_NODES, n < 128, k < 256
// Block: 256 threads, tile BM=64 rows x BN=128 cols (all), BK=32.
// Thread tile 4x8 (rows m = tm + 16*i, cols n = tn + 16*j) -> conflict-free
// scalar LDS with +1 padding.
// ---------------------------------------------------------------------------
#define BM 64
#define BK 32

__global__ __launch_bounds__(256) void gemm_lrelu_kernel(
    const float* __restrict__ F, const float* __restrict__ W)
{
    __shared__ float As[BK][BM + 1];     // As[k][m]
    __shared__ float Bs[BK][OUT_F + 1];  // Bs[k][n]

    const int tid = threadIdx.x;
    const int block_row = blockIdx.x * BM;
    const int tn = tid & 15;   // 0..15
    const int tm = tid >> 4;   // 0..15

    float acc[4][8];
#pragma unroll
    for (int i = 0; i < 4; ++i)
#pragma unroll
        for (int j = 0; j < 8; ++j) acc[i][j] = 0.f;

    for (int k0 = 0; k0 < IN_F; k0 += BK) {
        // Load A tile: 64 rows x 32 k = 512 float4, 2 per thread
#pragma unroll
        for (int t = 0; t < 2; ++t) {
            int idx = tid + t * 256;     // 0..511
            int r   = idx >> 3;          // 0..63
            int c4  = idx & 7;           // 0..7
            int grow = block_row + r;
            float4 v = make_float4(0.f, 0.f, 0.f, 0.f);
            if (grow < N_NODES)
                v = *reinterpret_cast<const float4*>(F + (size_t)grow * IN_F + k0 + c4 * 4);
            As[c4 * 4 + 0][r] = v.x;
            As[c4 * 4 + 1][r] = v.y;
            As[c4 * 4 + 2][r] = v.z;
            As[c4 * 4 + 3][r] = v.w;
        }
        // Load B tile: 128 rows(n) x 32 k = 1024 float4, 4 per thread
#pragma unroll
        for (int t = 0; t < 4; ++t) {
            int idx = tid + t * 256;     // 0..1023
            int n   = idx >> 3;          // 0..127
            int c4  = idx & 7;
            float4 v = *reinterpret_cast<const float4*>(W + (size_t)n * IN_F + k0 + c4 * 4);
            Bs[c4 * 4 + 0][n] = v.x;
            Bs[c4 * 4 + 1][n] = v.y;
            Bs[c4 * 4 + 2][n] = v.z;
            Bs[c4 * 4 + 3][n] = v.w;
        }
        __syncthreads();

#pragma unroll
        for (int k = 0; k < BK; ++k) {
            float a[4], b[8];
#pragma unroll
            for (int i = 0; i < 4; ++i) a[i] = As[k][tm + 16 * i];
#pragma unroll
            for (int j = 0; j < 8; ++j) b[j] = Bs[k][tn + 16 * j];
#pragma unroll
            for (int i = 0; i < 4; ++i)
#pragma unroll
                for (int j = 0; j < 8; ++j) acc[i][j] += a[i] * b[j];
        }
        __syncthreads();
    }

    // LeakyReLU + store to scratch
#pragma unroll
    for (int i = 0; i < 4; ++i) {
        int m = block_row + tm + 16 * i;
        if (m < N_NODES) {
            float* dst = g_support + (size_t)m * OUT_F;
#pragma unroll
            for (int j = 0; j < 8; ++j) {
                float x = acc[i][j];
                x = (x > 0.f) ? x : NEG_SLOPE * x;
                dst[tn + 16 * j] = x;
            }
        }
    }
}

// ---------------------------------------------------------------------------
// Kernel 2: edge scatter.  One warp per edge.
//   out[row] += val * support[col]   (128 floats = 32 lanes x float4)
// Vector reduction red.global.add.v4.f32 (sm_90+) -> 1 REDG.128 per lane.
// support (51.2 MB) is L2-resident, gathers are L2 hits.
// ---------------------------------------------------------------------------
__global__ __launch_bounds__(256) void spmm_scatter_kernel(
    const float* __restrict__ vals,
    const int*   __restrict__ rows,
    const int*   __restrict__ cols,
    float* __restrict__ out)
{
    const int warp = (blockIdx.x * blockDim.x + threadIdx.x) >> 5;
    const int lane = threadIdx.x & 31;
    if (warp >= N_EDGES) return;

    const int   r = rows[warp];
    const int   c = cols[warp];
    const float v = vals[warp];

    const float4* sp = reinterpret_cast<const float4*>(g_support) + (size_t)c * 32 + lane;
    float4 s = *sp;

    float4* op = reinterpret_cast<float4*>(out) + (size_t)r * 32 + lane;
    asm volatile(
        "red.global.add.v4.f32 [%0], {%1, %2, %3, %4};"
        :: "l"(op), "f"(s.x * v), "f"(s.y * v), "f"(s.z * v), "f"(s.w * v)
        : "memory");
}

// ---------------------------------------------------------------------------
// launch
// inputs (metadata order): features [N,256] f32, weight [128,256] f32,
//                          edge_vals [E] f32, edge_rows [E] i32, edge_cols [E] i32
// output: [N_NODES, 128] f32
// ---------------------------------------------------------------------------
extern "C" void kernel_launch(void* const* d_in, const int* in_sizes, int n_in,
                              void* d_out, int out_size)
{
    const float* features = (const float*)d_in[0];
    const float* weight   = (const float*)d_in[1];
    const float* evals    = (const float*)d_in[2];
    const int*   erows    = (const int*)d_in[3];
    const int*   ecols    = (const int*)d_in[4];
    float*       out      = (float*)d_out;

    // 1) dense GEMM + leaky relu -> g_support
    int gemm_blocks = (N_NODES + BM - 1) / BM;
    gemm_lrelu_kernel<<<gemm_blocks, 256>>>(features, weight);

    // 2) zero output (poisoned by harness)
    cudaMemsetAsync(d_out, 0, (size_t)out_size * sizeof(float), 0);

    // 3) scatter: one warp per edge, 8 warps per block
    int scatter_blocks = (N_EDGES + 7) / 8;
    spmm_scatter_kernel<<<scatter_blocks, 256>>>(evals, erows, ecols, out);
}

// round 3
// speedup vs baseline: 1.4614x; 1.4614x over previous
#include <cuda_runtime.h>
#include <cuda_bf16.h>
#include <cstdint>

#define N_NODES 100000
#define N_EDGES 3200000
#define IN_F    256
#define OUT_F   128
#define NEG_SLOPE 0.2f

// Scratch (static __device__ globals per allocation rules)
__device__ float g_support[(size_t)N_NODES * OUT_F];                 // 51.2 MB
__device__ unsigned long long g_sorted[(size_t)N_EDGES];             // 25.6 MB packed (col | val<<32)
__device__ int g_count[N_NODES];
__device__ int g_start[N_NODES + 1];
__device__ int g_cursor[N_NODES];

// ---------------------------------------------------------------------------
// Kernel 1: tiled fp32 GEMM + LeakyReLU  (unchanged from R1 — ~180us)
// ---------------------------------------------------------------------------
#define BM 64
#define BK 32

__global__ __launch_bounds__(256) void gemm_lrelu_kernel(
    const float* __restrict__ F, const float* __restrict__ W)
{
    __shared__ float As[BK][BM + 1];
    __shared__ float Bs[BK][OUT_F + 1];

    const int tid = threadIdx.x;
    const int block_row = blockIdx.x * BM;
    const int tn = tid & 15;
    const int tm = tid >> 4;

    float acc[4][8];
#pragma unroll
    for (int i = 0; i < 4; ++i)
#pragma unroll
        for (int j = 0; j < 8; ++j) acc[i][j] = 0.f;

    for (int k0 = 0; k0 < IN_F; k0 += BK) {
#pragma unroll
        for (int t = 0; t < 2; ++t) {
            int idx = tid + t * 256;
            int r   = idx >> 3;
            int c4  = idx & 7;
            int grow = block_row + r;
            float4 v = make_float4(0.f, 0.f, 0.f, 0.f);
            if (grow < N_NODES)
                v = *reinterpret_cast<const float4*>(F + (size_t)grow * IN_F + k0 + c4 * 4);
            As[c4 * 4 + 0][r] = v.x;
            As[c4 * 4 + 1][r] = v.y;
            As[c4 * 4 + 2][r] = v.z;
            As[c4 * 4 + 3][r] = v.w;
        }
#pragma unroll
        for (int t = 0; t < 4; ++t) {
            int idx = tid + t * 256;
            int n   = idx >> 3;
            int c4  = idx & 7;
            float4 v = *reinterpret_cast<const float4*>(W + (size_t)n * IN_F + k0 + c4 * 4);
            Bs[c4 * 4 + 0][n] = v.x;
            Bs[c4 * 4 + 1][n] = v.y;
            Bs[c4 * 4 + 2][n] = v.z;
            Bs[c4 * 4 + 3][n] = v.w;
        }
        __syncthreads();

#pragma unroll
        for (int k = 0; k < BK; ++k) {
            float a[4], b[8];
#pragma unroll
            for (int i = 0; i < 4; ++i) a[i] = As[k][tm + 16 * i];
#pragma unroll
            for (int j = 0; j < 8; ++j) b[j] = Bs[k][tn + 16 * j];
#pragma unroll
            for (int i = 0; i < 4; ++i)
#pragma unroll
                for (int j = 0; j < 8; ++j) acc[i][j] += a[i] * b[j];
        }
        __syncthreads();
    }

#pragma unroll
    for (int i = 0; i < 4; ++i) {
        int m = block_row + tm + 16 * i;
        if (m < N_NODES) {
            float* dst = g_support + (size_t)m * OUT_F;
#pragma unroll
            for (int j = 0; j < 8; ++j) {
                float x = acc[i][j];
                x = (x > 0.f) ? x : NEG_SLOPE * x;
                dst[tn + 16 * j] = x;
            }
        }
    }
}

// ---------------------------------------------------------------------------
// Sort pipeline: zero counts -> histogram -> scan -> bucket
// ---------------------------------------------------------------------------
__global__ __launch_bounds__(256) void zero_counts_kernel()
{
    int i = blockIdx.x * blockDim.x + threadIdx.x;
    if (i < N_NODES) g_count[i] = 0;
}

__global__ __launch_bounds__(256) void hist_kernel(const int* __restrict__ rows)
{
    int e = blockIdx.x * blockDim.x + threadIdx.x;
    if (e < N_EDGES) atomicAdd(&g_count[rows[e]], 1);
}

// Single-block scan over 100k counts with chunk prefetch.
__global__ __launch_bounds__(1024) void scan_kernel()
{
    __shared__ int warp_sums[32];
    __shared__ int s_carry;
    const int tid  = threadIdx.x;
    const int lane = tid & 31;
    const int wid  = tid >> 5;

    if (tid == 0) s_carry = 0;
    __syncthreads();

    int v_next = (tid < N_NODES) ? g_count[tid] : 0;

    for (int base = 0; base < N_NODES; base += 1024) {
        int v = v_next;
        int ni = base + 1024 + tid;
        v_next = (ni < N_NODES && base + 1024 < N_NODES) ? g_count[ni] : 0;

        // inclusive warp scan
        int x = v;
#pragma unroll
        for (int d = 1; d < 32; d <<= 1) {
            int t = __shfl_up_sync(0xffffffffu, x, d);
            if (lane >= d) x += t;
        }
        if (lane == 31) warp_sums[wid] = x;
        __syncthreads();
        if (tid < 32) {
            int w = warp_sums[tid];
#pragma unroll
            for (int d = 1; d < 32; d <<= 1) {
                int t = __shfl_up_sync(0xffffffffu, w, d);
                if (tid >= d) w += t;
            }
            warp_sums[tid] = w;
        }
        __syncthreads();
        int warp_prefix = (wid > 0) ? warp_sums[wid - 1] : 0;
        int incl = x + warp_prefix + s_carry;
        int excl = incl - v;
        int i = base + tid;
        if (i < N_NODES) { g_start[i] = excl; g_cursor[i] = excl; }
        __syncthreads();
        if (tid == 1023) s_carry = incl;
        __syncthreads();
    }
    if (tid == 0) g_start[N_NODES] = s_carry;   // == N_EDGES
}

__global__ __launch_bounds__(256) void bucket_kernel(
    const float* __restrict__ vals,
    const int*   __restrict__ rows,
    const int*   __restrict__ cols)
{
    int e = blockIdx.x * blockDim.x + threadIdx.x;
    if (e >= N_EDGES) return;
    int r = rows[e];
    int pos = atomicAdd(&g_cursor[r], 1);
    unsigned long long rec = (unsigned int)cols[e]
                           | ((unsigned long long)__float_as_uint(vals[e]) << 32);
    g_sorted[pos] = rec;
}

// ---------------------------------------------------------------------------
// Row accumulation: one warp per output row, accumulator in registers,
// fully-coalesced 512B gathers from L2-resident g_support, single write out.
// ---------------------------------------------------------------------------
__global__ __launch_bounds__(256) void row_accum_kernel(float* __restrict__ out)
{
    const int row  = blockIdx.x * 8 + (threadIdx.x >> 5);
    const int lane = threadIdx.x & 31;
    if (row >= N_NODES) return;

    const int beg = g_start[row];
    const int end = g_start[row + 1];

    const float4* __restrict__ sup4 = reinterpret_cast<const float4*>(g_support);

    float4 acc = make_float4(0.f, 0.f, 0.f, 0.f);

    int i = beg;
    // unroll-2 for memory-level parallelism
    for (; i + 1 < end; i += 2) {
        unsigned long long e0 = g_sorted[i];
        unsigned long long e1 = g_sorted[i + 1];
        int   c0 = (int)(e0 & 0xffffffffu);
        int   c1 = (int)(e1 & 0xffffffffu);
        float v0 = __uint_as_float((unsigned int)(e0 >> 32));
        float v1 = __uint_as_float((unsigned int)(e1 >> 32));
        float4 s0 = sup4[(size_t)c0 * 32 + lane];
        float4 s1 = sup4[(size_t)c1 * 32 + lane];
        acc.x += v0 * s0.x + v1 * s1.x;
        acc.y += v0 * s0.y + v1 * s1.y;
        acc.z += v0 * s0.z + v1 * s1.z;
        acc.w += v0 * s0.w + v1 * s1.w;
    }
    if (i < end) {
        unsigned long long e0 = g_sorted[i];
        int   c0 = (int)(e0 & 0xffffffffu);
        float v0 = __uint_as_float((unsigned int)(e0 >> 32));
        float4 s0 = sup4[(size_t)c0 * 32 + lane];
        acc.x += v0 * s0.x;
        acc.y += v0 * s0.y;
        acc.z += v0 * s0.z;
        acc.w += v0 * s0.w;
    }

    reinterpret_cast<float4*>(out)[(size_t)row * 32 + lane] = acc;
}

// ---------------------------------------------------------------------------
// launch
// ---------------------------------------------------------------------------
extern "C" void kernel_launch(void* const* d_in, const int* in_sizes, int n_in,
                              void* d_out, int out_size)
{
    const float* features = (const float*)d_in[0];
    const float* weight   = (const float*)d_in[1];
    const float* evals    = (const float*)d_in[2];
    const int*   erows    = (const int*)d_in[3];
    const int*   ecols    = (const int*)d_in[4];
    float*       out      = (float*)d_out;

    // Dense GEMM + lrelu -> g_support
    gemm_lrelu_kernel<<<(N_NODES + BM - 1) / BM, 256>>>(features, weight);

    // Counting sort of edges by destination row
    zero_counts_kernel<<<(N_NODES + 255) / 256, 256>>>();
    hist_kernel<<<(N_EDGES + 255) / 256, 256>>>(erows);
    scan_kernel<<<1, 1024>>>();
    bucket_kernel<<<(N_EDGES + 255) / 256, 256>>>(evals, erows, ecols);

    // Owner-computes reduction: one warp per row, no atomics, writes out once
    row_accum_kernel<<<(N_NODES + 7) / 8, 256>>>(out);
}

// round 5
// speedup vs baseline: 1.6257x; 1.1124x over previous
#include <cuda_runtime.h>
#include <cuda_fp16.h>
#include <cuda_bf16.h>
#include <cstdint>

#define N_NODES 100000
#define N_EDGES 3200000
#define IN_F    256
#define OUT_F   128
#define NEG_SLOPE 0.2f

#define SCAN_BLK 1024
#define NB ((N_NODES + SCAN_BLK - 1) / SCAN_BLK)   // 98 scan blocks

// Scratch (static __device__ globals per allocation rules)
__device__ __half g_support_h[(size_t)N_NODES * OUT_F];   // 25.6 MB fp16 support
__device__ unsigned long long g_sorted[(size_t)N_EDGES];  // packed (col | val<<32)
__device__ int g_count[N_NODES];
__device__ int g_start[N_NODES + 1];
__device__ int g_cursor[N_NODES];
__device__ int g_bsum[NB];
__device__ int g_boff[NB];

// ---------------------------------------------------------------------------
// Kernel 1: tiled fp32 GEMM + LeakyReLU, fp16 epilogue
// ---------------------------------------------------------------------------
#define BM 64
#define BK 32

__global__ __launch_bounds__(256) void gemm_lrelu_kernel(
    const float* __restrict__ F, const float* __restrict__ W)
{
    __shared__ float As[BK][BM + 1];
    __shared__ float Bs[BK][OUT_F + 1];

    const int tid = threadIdx.x;
    const int block_row = blockIdx.x * BM;
    const int tn = tid & 15;
    const int tm = tid >> 4;

    float acc[4][8];
#pragma unroll
    for (int i = 0; i < 4; ++i)
#pragma unroll
        for (int j = 0; j < 8; ++j) acc[i][j] = 0.f;

    for (int k0 = 0; k0 < IN_F; k0 += BK) {
#pragma unroll
        for (int t = 0; t < 2; ++t) {
            int idx = tid + t * 256;
            int r   = idx >> 3;
            int c4  = idx & 7;
            int grow = block_row + r;
            float4 v = make_float4(0.f, 0.f, 0.f, 0.f);
            if (grow < N_NODES)
                v = *reinterpret_cast<const float4*>(F + (size_t)grow * IN_F + k0 + c4 * 4);
            As[c4 * 4 + 0][r] = v.x;
            As[c4 * 4 + 1][r] = v.y;
            As[c4 * 4 + 2][r] = v.z;
            As[c4 * 4 + 3][r] = v.w;
        }
#pragma unroll
        for (int t = 0; t < 4; ++t) {
            int idx = tid + t * 256;
            int n   = idx >> 3;
            int c4  = idx & 7;
            float4 v = *reinterpret_cast<const float4*>(W + (size_t)n * IN_F + k0 + c4 * 4);
            Bs[c4 * 4 + 0][n] = v.x;
            Bs[c4 * 4 + 1][n] = v.y;
            Bs[c4 * 4 + 2][n] = v.z;
            Bs[c4 * 4 + 3][n] = v.w;
        }
        __syncthreads();

#pragma unroll
        for (int k = 0; k < BK; ++k) {
            float a[4], b[8];
#pragma unroll
            for (int i = 0; i < 4; ++i) a[i] = As[k][tm + 16 * i];
#pragma unroll
            for (int j = 0; j < 8; ++j) b[j] = Bs[k][tn + 16 * j];
#pragma unroll
            for (int i = 0; i < 4; ++i)
#pragma unroll
                for (int j = 0; j < 8; ++j) acc[i][j] += a[i] * b[j];
        }
        __syncthreads();
    }

#pragma unroll
    for (int i = 0; i < 4; ++i) {
        int m = block_row + tm + 16 * i;
        if (m < N_NODES) {
            __half* dst = g_support_h + (size_t)m * OUT_F;
#pragma unroll
            for (int j = 0; j < 8; ++j) {
                float x = acc[i][j];
                x = (x > 0.f) ? x : NEG_SLOPE * x;
                dst[tn + 16 * j] = __float2half_rn(x);
            }
        }
    }
}

// ---------------------------------------------------------------------------
// Histogram of destination rows
// ---------------------------------------------------------------------------
__global__ __launch_bounds__(256) void hist_kernel(const int* __restrict__ rows)
{
    int e = blockIdx.x * blockDim.x + threadIdx.x;
    if (e < N_EDGES) atomicAdd(&g_count[rows[e]], 1);
}

// ---------------------------------------------------------------------------
// Parallel 3-phase scan
// ---------------------------------------------------------------------------
// Phase A: per-block reduce of counts
__global__ __launch_bounds__(SCAN_BLK) void scan_reduce_kernel()
{
    __shared__ int wsum[32];
    const int tid = threadIdx.x;
    const int i = blockIdx.x * SCAN_BLK + tid;
    int v = (i < N_NODES) ? g_count[i] : 0;
#pragma unroll
    for (int d = 16; d > 0; d >>= 1) v += __shfl_down_sync(0xffffffffu, v, d);
    if ((tid & 31) == 0) wsum[tid >> 5] = v;
    __syncthreads();
    if (tid < 32) {
        int s = wsum[tid];
#pragma unroll
        for (int d = 16; d > 0; d >>= 1) s += __shfl_down_sync(0xffffffffu, s, d);
        if (tid == 0) g_bsum[blockIdx.x] = s;
    }
}

// Phase B: one small block scans the NB block sums (exclusive)
__global__ __launch_bounds__(128) void scan_bsums_kernel()
{
    __shared__ int wsum[4];
    const int tid  = threadIdx.x;
    const int lane = tid & 31;
    const int wid  = tid >> 5;
    int v = (tid < NB) ? g_bsum[tid] : 0;
    int x = v;
#pragma unroll
    for (int d = 1; d < 32; d <<= 1) {
        int t = __shfl_up_sync(0xffffffffu, x, d);
        if (lane >= d) x += t;
    }
    if (lane == 31) wsum[wid] = x;
    __syncthreads();
    if (tid < 4) {
        int w = wsum[tid];
#pragma unroll
        for (int d = 1; d < 4; d <<= 1) {
            int t = __shfl_up_sync(0x0000000fu, w, d);
            if (tid >= d) w += t;
        }
        wsum[tid] = w;
    }
    __syncthreads();
    int excl = x - v + ((wid > 0) ? wsum[wid - 1] : 0);
    if (tid < NB) g_boff[tid] = excl;
    if (tid == 0) g_start[N_NODES] = N_EDGES;
}

// Phase C: per-block inclusive scan + block offset -> exclusive starts
__global__ __launch_bounds__(SCAN_BLK) void scan_final_kernel()
{
    __shared__ int wsum[32];
    const int tid  = threadIdx.x;
    const int lane = tid & 31;
    const int wid  = tid >> 5;
    const int i = blockIdx.x * SCAN_BLK + tid;
    int v = (i < N_NODES) ? g_count[i] : 0;
    int x = v;
#pragma unroll
    for (int d = 1; d < 32; d <<= 1) {
        int t = __shfl_up_sync(0xffffffffu, x, d);
        if (lane >= d) x += t;
    }
    if (lane == 31) wsum[wid] = x;
    __syncthreads();
    if (tid < 32) {
        int w = wsum[tid];
#pragma unroll
        for (int d = 1; d < 32; d <<= 1) {
            int t = __shfl_up_sync(0xffffffffu, w, d);
            if (tid >= d) w += t;
        }
        wsum[tid] = w;
    }
    __syncthreads();
    int excl = x - v + ((wid > 0) ? wsum[wid - 1] : 0) + g_boff[blockIdx.x];
    if (i < N_NODES) { g_start[i] = excl; g_cursor[i] = excl; }
}

// ---------------------------------------------------------------------------
// Bucket edges into row-sorted order
// ---------------------------------------------------------------------------
__global__ __launch_bounds__(256) void bucket_kernel(
    const float* __restrict__ vals,
    const int*   __restrict__ rows,
    const int*   __restrict__ cols)
{
    int e = blockIdx.x * blockDim.x + threadIdx.x;
    if (e >= N_EDGES) return;
    int r = rows[e];
    int pos = atomicAdd(&g_cursor[r], 1);
    unsigned long long rec = (unsigned int)cols[e]
                           | ((unsigned long long)__float_as_uint(vals[e]) << 32);
    g_sorted[pos] = rec;
}

// ---------------------------------------------------------------------------
// Row accumulation: one warp per row; fp16 support gathers (256B/edge),
// fp32 register accumulators, single coalesced fp32 write.
// ---------------------------------------------------------------------------
__global__ __launch_bounds__(256) void row_accum_kernel(float* __restrict__ out)
{
    const int row  = blockIdx.x * 8 + (threadIdx.x >> 5);
    const int lane = threadIdx.x & 31;
    if (row >= N_NODES) return;

    const int beg = g_start[row];
    const int end = g_start[row + 1];

    const uint2* __restrict__ sup = reinterpret_cast<const uint2*>(g_support_h);

    float a0 = 0.f, a1 = 0.f, a2 = 0.f, a3 = 0.f;

    int i = beg;
    for (; i + 1 < end; i += 2) {
        unsigned long long e0 = g_sorted[i];
        unsigned long long e1 = g_sorted[i + 1];
        int   c0 = (int)(e0 & 0xffffffffu);
        int   c1 = (int)(e1 & 0xffffffffu);
        float v0 = __uint_as_float((unsigned int)(e0 >> 32));
        float v1 = __uint_as_float((unsigned int)(e1 >> 32));
        uint2 p0 = sup[(size_t)c0 * 32 + lane];
        uint2 p1 = sup[(size_t)c1 * 32 + lane];
        float2 f0a = __half22float2(*reinterpret_cast<__half2*>(&p0.x));
        float2 f0b = __half22float2(*reinterpret_cast<__half2*>(&p0.y));
        float2 f1a = __half22float2(*reinterpret_cast<__half2*>(&p1.x));
        float2 f1b = __half22float2(*reinterpret_cast<__half2*>(&p1.y));
        a0 += v0 * f0a.x + v1 * f1a.x;
        a1 += v0 * f0a.y + v1 * f1a.y;
        a2 += v0 * f0b.x + v1 * f1b.x;
        a3 += v0 * f0b.y + v1 * f1b.y;
    }
    if (i < end) {
        unsigned long long e0 = g_sorted[i];
        int   c0 = (int)(e0 & 0xffffffffu);
        float v0 = __uint_as_float((unsigned int)(e0 >> 32));
        uint2 p0 = sup[(size_t)c0 * 32 + lane];
        float2 f0a = __half22float2(*reinterpret_cast<__half2*>(&p0.x));
        float2 f0b = __half22float2(*reinterpret_cast<__half2*>(&p0.y));
        a0 += v0 * f0a.x;
        a1 += v0 * f0a.y;
        a2 += v0 * f0b.x;
        a3 += v0 * f0b.y;
    }

    reinterpret_cast<float4*>(out)[(size_t)row * 32 + lane] =
        make_float4(a0, a1, a2, a3);
}

// ---------------------------------------------------------------------------
// launch
// ---------------------------------------------------------------------------
extern "C" void kernel_launch(void* const* d_in, const int* in_sizes, int n_in,
                              void* d_out, int out_size)
{
    const float* features = (const float*)d_in[0];
    const float* weight   = (const float*)d_in[1];
    const float* evals    = (const float*)d_in[2];
    const int*   erows    = (const int*)d_in[3];
    const int*   ecols    = (const int*)d_in[4];
    float*       out      = (float*)d_out;

    // Dense GEMM + lrelu -> g_support_h (fp16)
    gemm_lrelu_kernel<<<(N_NODES + BM - 1) / BM, 256>>>(features, weight);

    // Counting sort of edges by destination row
    void* count_ptr = nullptr;
    cudaGetSymbolAddress(&count_ptr, g_count);
    cudaMemsetAsync(count_ptr, 0, sizeof(int) * N_NODES, 0);

    hist_kernel<<<(N_EDGES + 255) / 256, 256>>>(erows);
    scan_reduce_kernel<<<NB, SCAN_BLK>>>();
    scan_bsums_kernel<<<1, 128>>>();
    scan_final_kernel<<<NB, SCAN_BLK>>>();
    bucket_kernel<<<(N_EDGES + 255) / 256, 256>>>(evals, erows, ecols);

    // Owner-computes reduction: one warp per row, no atomics
    row_accum_kernel<<<(N_NODES + 7) / 8, 256>>>(out);
}

// round 6
// speedup vs baseline: 1.9787x; 1.2171x over previous
#include <cuda_runtime.h>
#include <cuda_fp16.h>
#include <cuda_bf16.h>
#include <mma.h>
#include <cstdint>

using namespace nvcuda;

#define N_NODES 100000
#define N_EDGES 3200000
#define IN_F    256
#define OUT_F   128
#define NEG_SLOPE 0.2f

#define SCAN_BLK 1024
#define NB ((N_NODES + SCAN_BLK - 1) / SCAN_BLK)

// Scratch (static __device__ globals per allocation rules)
__device__ __half g_support_h[(size_t)N_NODES * OUT_F];   // 25.6 MB fp16 support
__device__ unsigned long long g_sorted[(size_t)N_EDGES];  // packed (col | val<<32)
__device__ int g_count[N_NODES];
__device__ int g_start[N_NODES + 1];
__device__ int g_cursor[N_NODES];
__device__ int g_bsum[NB];
__device__ int g_boff[NB];

// ---------------------------------------------------------------------------
// Kernel 1: bf16 split-precision tensor-core GEMM + LeakyReLU, fp16 epilogue.
//   C = F @ W^T ;  f = fh + fl (bf16 split), w = wh + wl
//   C ≈ fh*wh + fh*wl + fl*wh    (fl*wl ~2^-18 rel, dropped)
// Block: 256 thr (8 warps, 4x2), tile 128x128, KC=32 per stage.
// ---------------------------------------------------------------------------
#define GBM 128
#define GKC 32
#define A_LD 40            // KC + 8 pad (bf16 elems)
#define C_LD 68            // 64 + 4 pad (fp32 elems)

__device__ __forceinline__ void split_bf16(float x, __nv_bfloat16& h, __nv_bfloat16& l)
{
    h = __float2bfloat16(x);
    l = __float2bfloat16(x - __bfloat162float(h));
}

__global__ __launch_bounds__(256) void gemm_tc_kernel(
    const float* __restrict__ F, const float* __restrict__ W)
{
    __shared__ union {
        struct {
            __nv_bfloat16 Ah[GBM * A_LD];
            __nv_bfloat16 Al[GBM * A_LD];
            __nv_bfloat16 Bh[OUT_F * A_LD];
            __nv_bfloat16 Bl[OUT_F * A_LD];
        } op;                               // 40 KB
        float Cs[GBM * C_LD];               // 34.8 KB (epilogue staging, half of N)
    } sm;

    const int tid = threadIdx.x;
    const int wid = tid >> 5;
    const int wm  = wid & 3;        // warp row   (4)  -> rows wm*32 .. +32
    const int wn  = wid >> 2;       // warp col   (2)  -> cols wn*64 .. +64
    const int block_row = blockIdx.x * GBM;

    wmma::fragment<wmma::accumulator, 16, 16, 16, float> acc[2][4];
#pragma unroll
    for (int i = 0; i < 2; ++i)
#pragma unroll
        for (int j = 0; j < 4; ++j) wmma::fill_fragment(acc[i][j], 0.f);

    for (int k0 = 0; k0 < IN_F; k0 += GKC) {
        __syncthreads();
        // Load + split-convert A tile (128 rows x 32 k): 1024 float4, 4/thread
#pragma unroll
        for (int t = 0; t < 4; ++t) {
            int idx = tid + t * 256;
            int r   = idx >> 3;
            int c4  = idx & 7;
            int grow = block_row + r;
            float4 v = make_float4(0.f, 0.f, 0.f, 0.f);
            if (grow < N_NODES)
                v = *reinterpret_cast<const float4*>(F + (size_t)grow * IN_F + k0 + c4 * 4);
            __nv_bfloat16 h, l;
            int base = r * A_LD + c4 * 4;
            split_bf16(v.x, h, l); sm.op.Ah[base + 0] = h; sm.op.Al[base + 0] = l;
            split_bf16(v.y, h, l); sm.op.Ah[base + 1] = h; sm.op.Al[base + 1] = l;
            split_bf16(v.z, h, l); sm.op.Ah[base + 2] = h; sm.op.Al[base + 2] = l;
            split_bf16(v.w, h, l); sm.op.Ah[base + 3] = h; sm.op.Al[base + 3] = l;
        }
        // Load + split-convert B tile (128 n x 32 k): 1024 float4, 4/thread
#pragma unroll
        for (int t = 0; t < 4; ++t) {
            int idx = tid + t * 256;
            int n   = idx >> 3;
            int c4  = idx & 7;
            float4 v = *reinterpret_cast<const float4*>(W + (size_t)n * IN_F + k0 + c4 * 4);
            __nv_bfloat16 h, l;
            int base = n * A_LD + c4 * 4;
            split_bf16(v.x, h, l); sm.op.Bh[base + 0] = h; sm.op.Bl[base + 0] = l;
            split_bf16(v.y, h, l); sm.op.Bh[base + 1] = h; sm.op.Bl[base + 1] = l;
            split_bf16(v.z, h, l); sm.op.Bh[base + 2] = h; sm.op.Bl[base + 2] = l;
            split_bf16(v.w, h, l); sm.op.Bh[base + 3] = h; sm.op.Bl[base + 3] = l;
        }
        __syncthreads();

#pragma unroll
        for (int kk = 0; kk < GKC; kk += 16) {
            wmma::fragment<wmma::matrix_a, 16, 16, 16, __nv_bfloat16, wmma::row_major> a_h[2], a_l[2];
#pragma unroll
            for (int i = 0; i < 2; ++i) {
                int mrow = wm * 32 + i * 16;
                wmma::load_matrix_sync(a_h[i], &sm.op.Ah[mrow * A_LD + kk], A_LD);
                wmma::load_matrix_sync(a_l[i], &sm.op.Al[mrow * A_LD + kk], A_LD);
            }
#pragma unroll
            for (int j = 0; j < 4; ++j) {
                int ncol = wn * 64 + j * 16;
                wmma::fragment<wmma::matrix_b, 16, 16, 16, __nv_bfloat16, wmma::col_major> b_h, b_l;
                wmma::load_matrix_sync(b_h, &sm.op.Bh[ncol * A_LD + kk], A_LD);
                wmma::load_matrix_sync(b_l, &sm.op.Bl[ncol * A_LD + kk], A_LD);
#pragma unroll
                for (int i = 0; i < 2; ++i) {
                    wmma::mma_sync(acc[i][j], a_h[i], b_h, acc[i][j]);
                    wmma::mma_sync(acc[i][j], a_h[i], b_l, acc[i][j]);
                    wmma::mma_sync(acc[i][j], a_l[i], b_h, acc[i][j]);
                }
            }
        }
    }

    // Epilogue: two column-half passes through the 128x64 fp32 staging buffer.
#pragma unroll
    for (int p = 0; p < 2; ++p) {
        __syncthreads();
        if (wn == p) {
#pragma unroll
            for (int i = 0; i < 2; ++i)
#pragma unroll
                for (int j = 0; j < 4; ++j)
                    wmma::store_matrix_sync(&sm.Cs[(wm * 32 + i * 16) * C_LD + j * 16],
                                            acc[i][j], C_LD, wmma::mem_row_major);
        }
        __syncthreads();
        // 128 rows x 64 cols -> 4096 half2-pairs? (32 half2/row) -> 16/thread
#pragma unroll
        for (int t = 0; t < 16; ++t) {
            int idx = tid + t * 256;        // 0..4095
            int r   = idx >> 5;             // 0..127
            int h2  = idx & 31;             // 0..31
            int grow = block_row + r;
            if (grow < N_NODES) {
                float x0 = sm.Cs[r * C_LD + h2 * 2 + 0];
                float x1 = sm.Cs[r * C_LD + h2 * 2 + 1];
                x0 = (x0 > 0.f) ? x0 : NEG_SLOPE * x0;
                x1 = (x1 > 0.f) ? x1 : NEG_SLOPE * x1;
                __half2* dst = reinterpret_cast<__half2*>(
                    g_support_h + (size_t)grow * OUT_F + p * 64);
                dst[h2] = __floats2half2_rn(x0, x1);
            }
        }
    }
}

// ---------------------------------------------------------------------------
// Histogram of destination rows
// ---------------------------------------------------------------------------
__global__ __launch_bounds__(256) void hist_kernel(const int* __restrict__ rows)
{
    int e = blockIdx.x * blockDim.x + threadIdx.x;
    if (e < N_EDGES) atomicAdd(&g_count[rows[e]], 1);
}

// ---------------------------------------------------------------------------
// Parallel 3-phase scan
// ---------------------------------------------------------------------------
__global__ __launch_bounds__(SCAN_BLK) void scan_reduce_kernel()
{
    __shared__ int wsum[32];
    const int tid = threadIdx.x;
    const int i = blockIdx.x * SCAN_BLK + tid;
    int v = (i < N_NODES) ? g_count[i] : 0;
#pragma unroll
    for (int d = 16; d > 0; d >>= 1) v += __shfl_down_sync(0xffffffffu, v, d);
    if ((tid & 31) == 0) wsum[tid >> 5] = v;
    __syncthreads();
    if (tid < 32) {
        int s = wsum[tid];
#pragma unroll
        for (int d = 16; d > 0; d >>= 1) s += __shfl_down_sync(0xffffffffu, s, d);
        if (tid == 0) g_bsum[blockIdx.x] = s;
    }
}

__global__ __launch_bounds__(128) void scan_bsums_kernel()
{
    __shared__ int wsum[4];
    const int tid  = threadIdx.x;
    const int lane = tid & 31;
    const int wid  = tid >> 5;
    int v = (tid < NB) ? g_bsum[tid] : 0;
    int x = v;
#pragma unroll
    for (int d = 1; d < 32; d <<= 1) {
        int t = __shfl_up_sync(0xffffffffu, x, d);
        if (lane >= d) x += t;
    }
    if (lane == 31) wsum[wid] = x;
    __syncthreads();
    if (tid < 4) {
        int w = wsum[tid];
#pragma unroll
        for (int d = 1; d < 4; d <<= 1) {
            int t = __shfl_up_sync(0x0000000fu, w, d);
            if (tid >= d) w += t;
        }
        wsum[tid] = w;
    }
    __syncthreads();
    int excl = x - v + ((wid > 0) ? wsum[wid - 1] : 0);
    if (tid < NB) g_boff[tid] = excl;
    if (tid == 0) g_start[N_NODES] = N_EDGES;
}

__global__ __launch_bounds__(SCAN_BLK) void scan_final_kernel()
{
    __shared__ int wsum[32];
    const int tid  = threadIdx.x;
    const int lane = tid & 31;
    const int wid  = tid >> 5;
    const int i = blockIdx.x * SCAN_BLK + tid;
    int v = (i < N_NODES) ? g_count[i] : 0;
    int x = v;
#pragma unroll
    for (int d = 1; d < 32; d <<= 1) {
        int t = __shfl_up_sync(0xffffffffu, x, d);
        if (lane >= d) x += t;
    }
    if (lane == 31) wsum[wid] = x;
    __syncthreads();
    if (tid < 32) {
        int w = wsum[tid];
#pragma unroll
        for (int d = 1; d < 32; d <<= 1) {
            int t = __shfl_up_sync(0xffffffffu, w, d);
            if (tid >= d) w += t;
        }
        wsum[tid] = w;
    }
    __syncthreads();
    int excl = x - v + ((wid > 0) ? wsum[wid - 1] : 0) + g_boff[blockIdx.x];
    if (i < N_NODES) { g_start[i] = excl; g_cursor[i] = excl; }
}

// ---------------------------------------------------------------------------
// Bucket edges into row-sorted order
// ---------------------------------------------------------------------------
__global__ __launch_bounds__(256) void bucket_kernel(
    const float* __restrict__ vals,
    const int*   __restrict__ rows,
    const int*   __restrict__ cols)
{
    int e = blockIdx.x * blockDim.x + threadIdx.x;
    if (e >= N_EDGES) return;
    int r = rows[e];
    int pos = atomicAdd(&g_cursor[r], 1);
    unsigned long long rec = (unsigned int)cols[e]
                           | ((unsigned long long)__float_as_uint(vals[e]) << 32);
    g_sorted[pos] = rec;
}

// ---------------------------------------------------------------------------
// Row accumulation: one warp per row; fp16 gathers, fp32 accumulators.
// ---------------------------------------------------------------------------
__global__ __launch_bounds__(256) void row_accum_kernel(float* __restrict__ out)
{
    const int row  = blockIdx.x * 8 + (threadIdx.x >> 5);
    const int lane = threadIdx.x & 31;
    if (row >= N_NODES) return;

    const int beg = g_start[row];
    const int end = g_start[row + 1];

    const uint2* __restrict__ sup = reinterpret_cast<const uint2*>(g_support_h);

    float a0 = 0.f, a1 = 0.f, a2 = 0.f, a3 = 0.f;

    int i = beg;
    for (; i + 1 < end; i += 2) {
        unsigned long long e0 = g_sorted[i];
        unsigned long long e1 = g_sorted[i + 1];
        int   c0 = (int)(e0 & 0xffffffffu);
        int   c1 = (int)(e1 & 0xffffffffu);
        float v0 = __uint_as_float((unsigned int)(e0 >> 32));
        float v1 = __uint_as_float((unsigned int)(e1 >> 32));
        uint2 p0 = sup[(size_t)c0 * 32 + lane];
        uint2 p1 = sup[(size_t)c1 * 32 + lane];
        float2 f0a = __half22float2(*reinterpret_cast<__half2*>(&p0.x));
        float2 f0b = __half22float2(*reinterpret_cast<__half2*>(&p0.y));
        float2 f1a = __half22float2(*reinterpret_cast<__half2*>(&p1.x));
        float2 f1b = __half22float2(*reinterpret_cast<__half2*>(&p1.y));
        a0 += v0 * f0a.x + v1 * f1a.x;
        a1 += v0 * f0a.y + v1 * f1a.y;
        a2 += v0 * f0b.x + v1 * f1b.x;
        a3 += v0 * f0b.y + v1 * f1b.y;
    }
    if (i < end) {
        unsigned long long e0 = g_sorted[i];
        int   c0 = (int)(e0 & 0xffffffffu);
        float v0 = __uint_as_float((unsigned int)(e0 >> 32));
        uint2 p0 = sup[(size_t)c0 * 32 + lane];
        float2 f0a = __half22float2(*reinterpret_cast<__half2*>(&p0.x));
        float2 f0b = __half22float2(*reinterpret_cast<__half2*>(&p0.y));
        a0 += v0 * f0a.x;
        a1 += v0 * f0a.y;
        a2 += v0 * f0b.x;
        a3 += v0 * f0b.y;
    }

    reinterpret_cast<float4*>(out)[(size_t)row * 32 + lane] =
        make_float4(a0, a1, a2, a3);
}

// ---------------------------------------------------------------------------
// launch
// ---------------------------------------------------------------------------
extern "C" void kernel_launch(void* const* d_in, const int* in_sizes, int n_in,
                              void* d_out, int out_size)
{
    const float* features = (const float*)d_in[0];
    const float* weight   = (const float*)d_in[1];
    const float* evals    = (const float*)d_in[2];
    const int*   erows    = (const int*)d_in[3];
    const int*   ecols    = (const int*)d_in[4];
    float*       out      = (float*)d_out;

    // Tensor-core GEMM + lrelu -> g_support_h (fp16)
    gemm_tc_kernel<<<(N_NODES + GBM - 1) / GBM, 256>>>(features, weight);

    // Counting sort of edges by destination row
    void* count_ptr = nullptr;
    cudaGetSymbolAddress(&count_ptr, g_count);
    cudaMemsetAsync(count_ptr, 0, sizeof(int) * N_NODES, 0);

    hist_kernel<<<(N_EDGES + 255) / 256, 256>>>(erows);
    scan_reduce_kernel<<<NB, SCAN_BLK>>>();
    scan_bsums_kernel<<<1, 128>>>();
    scan_final_kernel<<<NB, SCAN_BLK>>>();
    bucket_kernel<<<(N_EDGES + 255) / 256, 256>>>(evals, erows, ecols);

    // Owner-computes reduction: one warp per row, no atomics
    row_accum_kernel<<<(N_NODES + 7) / 8, 256>>>(out);
}

// round 7
// speedup vs baseline: 2.1382x; 1.0806x over previous
#include <cuda_runtime.h>
#include <cuda_fp16.h>
#include <cuda_bf16.h>
#include <mma.h>
#include <cstdint>

using namespace nvcuda;

#define N_NODES 100000
#define N_EDGES 3200000
#define IN_F    256
#define OUT_F   128
#define NEG_SLOPE 0.2f

#define SCAN_BLK 1024
#define NB ((N_NODES + SCAN_BLK - 1) / SCAN_BLK)

// Scratch (static __device__ globals per allocation rules)
__device__ __half g_support_h[(size_t)N_NODES * OUT_F];   // 25.6 MB fp16 support
__device__ unsigned long long g_sorted[(size_t)N_EDGES];  // packed (col | val<<32)
__device__ int g_count[N_NODES];
__device__ int g_start[N_NODES + 1];
__device__ int g_cursor[N_NODES];
__device__ int g_bsum[NB];
__device__ int g_boff[NB];

// ---------------------------------------------------------------------------
// Kernel 1: bf16 split-precision tensor-core GEMM + LeakyReLU, fp16 epilogue.
//   C ≈ fh*wh + fh*wl + fl*wh  (fl*wl dropped, ~2^-18 rel)
// Software pipelined: global loads of K-step i+1 issue before MMAs of step i.
// ---------------------------------------------------------------------------
#define GBM 128
#define GKC 32
#define K_ITERS (IN_F / GKC)     // 8
#define A_LD 40                  // KC + 8 pad (bf16)
#define C_LD 68                  // 64 + 4 pad (fp32)

__device__ __forceinline__ void split_bf16(float x, __nv_bfloat16& h, __nv_bfloat16& l)
{
    h = __float2bfloat16(x);
    l = __float2bfloat16(x - __bfloat162float(h));
}

__global__ __launch_bounds__(256) void gemm_tc_kernel(
    const float* __restrict__ F, const float* __restrict__ W)
{
    __shared__ union {
        struct {
            __nv_bfloat16 Ah[GBM * A_LD];
            __nv_bfloat16 Al[GBM * A_LD];
            __nv_bfloat16 Bh[OUT_F * A_LD];
            __nv_bfloat16 Bl[OUT_F * A_LD];
        } op;                               // 40 KB
        float Cs[GBM * C_LD];               // 34.8 KB (epilogue staging, half N)
    } sm;

    const int tid = threadIdx.x;
    const int wid = tid >> 5;
    const int wm  = wid & 3;        // warp row (4): rows wm*32..+32
    const int wn  = wid >> 2;       // warp col (2): cols wn*64..+64
    const int block_row = blockIdx.x * GBM;

    // Per-thread load coordinates (fixed across K-steps)
    const int a_r  = tid >> 3;            // 0..31 (+t*32)
    const int a_c4 = tid & 7;

    wmma::fragment<wmma::accumulator, 16, 16, 16, float> acc[2][4];
#pragma unroll
    for (int i = 0; i < 2; ++i)
#pragma unroll
        for (int j = 0; j < 4; ++j) wmma::fill_fragment(acc[i][j], 0.f);

    float4 aReg[4], bReg[4];

    // ---- load tile for k0 into registers ----
    auto loadA = [&](int t, int k0) -> float4 {
        int r = a_r + t * 32;
        int grow = block_row + r;
        if (grow < N_NODES)
            return *reinterpret_cast<const float4*>(F + (size_t)grow * IN_F + k0 + a_c4 * 4);
        return make_float4(0.f, 0.f, 0.f, 0.f);
    };
    auto loadB = [&](int t, int k0) -> float4 {
        int n = a_r + t * 32;
        return *reinterpret_cast<const float4*>(W + (size_t)n * IN_F + k0 + a_c4 * 4);
    };

    // prologue: tile 0
#pragma unroll
    for (int t = 0; t < 4; ++t) { aReg[t] = loadA(t, 0); bReg[t] = loadB(t, 0); }

#pragma unroll 1
    for (int it = 0; it < K_ITERS; ++it) {
        // store current regs -> smem (split convert)
#pragma unroll
        for (int t = 0; t < 4; ++t) {
            int r = a_r + t * 32;
            int base = r * A_LD + a_c4 * 4;
            __nv_bfloat16 h, l;
            split_bf16(aReg[t].x, h, l); sm.op.Ah[base + 0] = h; sm.op.Al[base + 0] = l;
            split_bf16(aReg[t].y, h, l); sm.op.Ah[base + 1] = h; sm.op.Al[base + 1] = l;
            split_bf16(aReg[t].z, h, l); sm.op.Ah[base + 2] = h; sm.op.Al[base + 2] = l;
            split_bf16(aReg[t].w, h, l); sm.op.Ah[base + 3] = h; sm.op.Al[base + 3] = l;
            split_bf16(bReg[t].x, h, l); sm.op.Bh[base + 0] = h; sm.op.Bl[base + 0] = l;
            split_bf16(bReg[t].y, h, l); sm.op.Bh[base + 1] = h; sm.op.Bl[base + 1] = l;
            split_bf16(bReg[t].z, h, l); sm.op.Bh[base + 2] = h; sm.op.Bl[base + 2] = l;
            split_bf16(bReg[t].w, h, l); sm.op.Bh[base + 3] = h; sm.op.Bl[base + 3] = l;
        }
        __syncthreads();

        // prefetch next tile into registers (overlaps with MMAs below)
        if (it + 1 < K_ITERS) {
            int k0 = (it + 1) * GKC;
#pragma unroll
            for (int t = 0; t < 4; ++t) { aReg[t] = loadA(t, k0); bReg[t] = loadB(t, k0); }
        }

        // MMAs on current smem stage
#pragma unroll
        for (int kk = 0; kk < GKC; kk += 16) {
            wmma::fragment<wmma::matrix_a, 16, 16, 16, __nv_bfloat16, wmma::row_major> a_h[2], a_l[2];
#pragma unroll
            for (int i = 0; i < 2; ++i) {
                int mrow = wm * 32 + i * 16;
                wmma::load_matrix_sync(a_h[i], &sm.op.Ah[mrow * A_LD + kk], A_LD);
                wmma::load_matrix_sync(a_l[i], &sm.op.Al[mrow * A_LD + kk], A_LD);
            }
#pragma unroll
            for (int j = 0; j < 4; ++j) {
                int ncol = wn * 64 + j * 16;
                wmma::fragment<wmma::matrix_b, 16, 16, 16, __nv_bfloat16, wmma::col_major> b_h, b_l;
                wmma::load_matrix_sync(b_h, &sm.op.Bh[ncol * A_LD + kk], A_LD);
                wmma::load_matrix_sync(b_l, &sm.op.Bl[ncol * A_LD + kk], A_LD);
#pragma unroll
                for (int i = 0; i < 2; ++i) {
                    wmma::mma_sync(acc[i][j], a_h[i], b_h, acc[i][j]);
                    wmma::mma_sync(acc[i][j], a_h[i], b_l, acc[i][j]);
                    wmma::mma_sync(acc[i][j], a_l[i], b_h, acc[i][j]);
                }
            }
        }
        __syncthreads();
    }

    // Epilogue: two column-half passes through 128x64 fp32 staging.
#pragma unroll
    for (int p = 0; p < 2; ++p) {
        if (wn == p) {
#pragma unroll
            for (int i = 0; i < 2; ++i)
#pragma unroll
                for (int j = 0; j < 4; ++j)
                    wmma::store_matrix_sync(&sm.Cs[(wm * 32 + i * 16) * C_LD + j * 16],
                                            acc[i][j], C_LD, wmma::mem_row_major);
        }
        __syncthreads();
#pragma unroll
        for (int t = 0; t < 16; ++t) {
            int idx = tid + t * 256;        // 0..4095
            int r   = idx >> 5;             // 0..127
            int h2  = idx & 31;             // 0..31
            int grow = block_row + r;
            if (grow < N_NODES) {
                float x0 = sm.Cs[r * C_LD + h2 * 2 + 0];
                float x1 = sm.Cs[r * C_LD + h2 * 2 + 1];
                x0 = (x0 > 0.f) ? x0 : NEG_SLOPE * x0;
                x1 = (x1 > 0.f) ? x1 : NEG_SLOPE * x1;
                __half2* dst = reinterpret_cast<__half2*>(
                    g_support_h + (size_t)grow * OUT_F + p * 64);
                dst[h2] = __floats2half2_rn(x0, x1);
            }
        }
        __syncthreads();
    }
}

// ---------------------------------------------------------------------------
// Histogram of destination rows
// ---------------------------------------------------------------------------
__global__ __launch_bounds__(256) void hist_kernel(const int* __restrict__ rows)
{
    int e = blockIdx.x * blockDim.x + threadIdx.x;
    if (e < N_EDGES) atomicAdd(&g_count[rows[e]], 1);
}

// ---------------------------------------------------------------------------
// Parallel 3-phase scan
// ---------------------------------------------------------------------------
__global__ __launch_bounds__(SCAN_BLK) void scan_reduce_kernel()
{
    __shared__ int wsum[32];
    const int tid = threadIdx.x;
    const int i = blockIdx.x * SCAN_BLK + tid;
    int v = (i < N_NODES) ? g_count[i] : 0;
#pragma unroll
    for (int d = 16; d > 0; d >>= 1) v += __shfl_down_sync(0xffffffffu, v, d);
    if ((tid & 31) == 0) wsum[tid >> 5] = v;
    __syncthreads();
    if (tid < 32) {
        int s = wsum[tid];
#pragma unroll
        for (int d = 16; d > 0; d >>= 1) s += __shfl_down_sync(0xffffffffu, s, d);
        if (tid == 0) g_bsum[blockIdx.x] = s;
    }
}

__global__ __launch_bounds__(128) void scan_bsums_kernel()
{
    __shared__ int wsum[4];
    const int tid  = threadIdx.x;
    const int lane = tid & 31;
    const int wid  = tid >> 5;
    int v = (tid < NB) ? g_bsum[tid] : 0;
    int x = v;
#pragma unroll
    for (int d = 1; d < 32; d <<= 1) {
        int t = __shfl_up_sync(0xffffffffu, x, d);
        if (lane >= d) x += t;
    }
    if (lane == 31) wsum[wid] = x;
    __syncthreads();
    if (tid < 4) {
        int w = wsum[tid];
#pragma unroll
        for (int d = 1; d < 4; d <<= 1) {
            int t = __shfl_up_sync(0x0000000fu, w, d);
            if (tid >= d) w += t;
        }
        wsum[tid] = w;
    }
    __syncthreads();
    int excl = x - v + ((wid > 0) ? wsum[wid - 1] : 0);
    if (tid < NB) g_boff[tid] = excl;
    if (tid == 0) g_start[N_NODES] = N_EDGES;
}

__global__ __launch_bounds__(SCAN_BLK) void scan_final_kernel()
{
    __shared__ int wsum[32];
    const int tid  = threadIdx.x;
    const int lane = tid & 31;
    const int wid  = tid >> 5;
    const int i = blockIdx.x * SCAN_BLK + tid;
    int v = (i < N_NODES) ? g_count[i] : 0;
    int x = v;
#pragma unroll
    for (int d = 1; d < 32; d <<= 1) {
        int t = __shfl_up_sync(0xffffffffu, x, d);
        if (lane >= d) x += t;
    }
    if (lane == 31) wsum[wid] = x;
    __syncthreads();
    if (tid < 32) {
        int w = wsum[tid];
#pragma unroll
        for (int d = 1; d < 32; d <<= 1) {
            int t = __shfl_up_sync(0xffffffffu, w, d);
            if (tid >= d) w += t;
        }
        wsum[tid] = w;
    }
    __syncthreads();
    int excl = x - v + ((wid > 0) ? wsum[wid - 1] : 0) + g_boff[blockIdx.x];
    if (i < N_NODES) { g_start[i] = excl; g_cursor[i] = excl; }
}

// ---------------------------------------------------------------------------
// Bucket edges into row-sorted order
// ---------------------------------------------------------------------------
__global__ __launch_bounds__(256) void bucket_kernel(
    const float* __restrict__ vals,
    const int*   __restrict__ rows,
    const int*   __restrict__ cols)
{
    int e = blockIdx.x * blockDim.x + threadIdx.x;
    if (e >= N_EDGES) return;
    int r = rows[e];
    int pos = atomicAdd(&g_cursor[r], 1);
    unsigned long long rec = (unsigned int)cols[e]
                           | ((unsigned long long)__float_as_uint(vals[e]) << 32);
    g_sorted[pos] = rec;
}

// ---------------------------------------------------------------------------
// Row accumulation: one warp per row; fp16 gathers (256B/edge), unroll-4 for
// MLP, fp32 register accumulators, single coalesced fp32 write.
// ---------------------------------------------------------------------------
__global__ __launch_bounds__(256) void row_accum_kernel(float* __restrict__ out)
{
    const int row  = blockIdx.x * 8 + (threadIdx.x >> 5);
    const int lane = threadIdx.x & 31;
    if (row >= N_NODES) return;

    const int beg = g_start[row];
    const int end = g_start[row + 1];

    const uint2* __restrict__ sup = reinterpret_cast<const uint2*>(g_support_h);

    float a0 = 0.f, a1 = 0.f, a2 = 0.f, a3 = 0.f;

    int i = beg;
    for (; i + 3 < end; i += 4) {
        unsigned long long e0 = g_sorted[i + 0];
        unsigned long long e1 = g_sorted[i + 1];
        unsigned long long e2 = g_sorted[i + 2];
        unsigned long long e3 = g_sorted[i + 3];
        int c0 = (int)(e0 & 0xffffffffu);
        int c1 = (int)(e1 & 0xffffffffu);
        int c2 = (int)(e2 & 0xffffffffu);
        int c3 = (int)(e3 & 0xffffffffu);
        float v0 = __uint_as_float((unsigned int)(e0 >> 32));
        float v1 = __uint_as_float((unsigned int)(e1 >> 32));
        float v2 = __uint_as_float((unsigned int)(e2 >> 32));
        float v3 = __uint_as_float((unsigned int)(e3 >> 32));
        uint2 p0 = sup[(size_t)c0 * 32 + lane];
        uint2 p1 = sup[(size_t)c1 * 32 + lane];
        uint2 p2 = sup[(size_t)c2 * 32 + lane];
        uint2 p3 = sup[(size_t)c3 * 32 + lane];
        float2 f;
        f = __half22float2(*reinterpret_cast<__half2*>(&p0.x)); a0 += v0 * f.x; a1 += v0 * f.y;
        f = __half22float2(*reinterpret_cast<__half2*>(&p0.y)); a2 += v0 * f.x; a3 += v0 * f.y;
        f = __half22float2(*reinterpret_cast<__half2*>(&p1.x)); a0 += v1 * f.x; a1 += v1 * f.y;
        f = __half22float2(*reinterpret_cast<__half2*>(&p1.y)); a2 += v1 * f.x; a3 += v1 * f.y;
        f = __half22float2(*reinterpret_cast<__half2*>(&p2.x)); a0 += v2 * f.x; a1 += v2 * f.y;
        f = __half22float2(*reinterpret_cast<__half2*>(&p2.y)); a2 += v2 * f.x; a3 += v2 * f.y;
        f = __half22float2(*reinterpret_cast<__half2*>(&p3.x)); a0 += v3 * f.x; a1 += v3 * f.y;
        f = __half22float2(*reinterpret_cast<__half2*>(&p3.y)); a2 += v3 * f.x; a3 += v3 * f.y;
    }
    for (; i < end; ++i) {
        unsigned long long e0 = g_sorted[i];
        int   c0 = (int)(e0 & 0xffffffffu);
        float v0 = __uint_as_float((unsigned int)(e0 >> 32));
        uint2 p0 = sup[(size_t)c0 * 32 + lane];
        float2 f;
        f = __half22float2(*reinterpret_cast<__half2*>(&p0.x)); a0 += v0 * f.x; a1 += v0 * f.y;
        f = __half22float2(*reinterpret_cast<__half2*>(&p0.y)); a2 += v0 * f.x; a3 += v0 * f.y;
    }

    reinterpret_cast<float4*>(out)[(size_t)row * 32 + lane] =
        make_float4(a0, a1, a2, a3);
}

// ---------------------------------------------------------------------------
// launch
// ---------------------------------------------------------------------------
extern "C" void kernel_launch(void* const* d_in, const int* in_sizes, int n_in,
                              void* d_out, int out_size)
{
    const float* features = (const float*)d_in[0];
    const float* weight   = (const float*)d_in[1];
    const float* evals    = (const float*)d_in[2];
    const int*   erows    = (const int*)d_in[3];
    const int*   ecols    = (const int*)d_in[4];
    float*       out      = (float*)d_out;

    // Tensor-core GEMM + lrelu -> g_support_h (fp16)
    gemm_tc_kernel<<<(N_NODES + GBM - 1) / GBM, 256>>>(features, weight);

    // Counting sort of edges by destination row
    void* count_ptr = nullptr;
    cudaGetSymbolAddress(&count_ptr, g_count);
    cudaMemsetAsync(count_ptr, 0, sizeof(int) * N_NODES, 0);

    hist_kernel<<<(N_EDGES + 255) / 256, 256>>>(erows);
    scan_reduce_kernel<<<NB, SCAN_BLK>>>();
    scan_bsums_kernel<<<1, 128>>>();
    scan_final_kernel<<<NB, SCAN_BLK>>>();
    bucket_kernel<<<(N_EDGES + 255) / 256, 256>>>(evals, erows, ecols);

    // Owner-computes reduction: one warp per row, no atomics
    row_accum_kernel<<<(N_NODES + 7) / 8, 256>>>(out);
}

// round 8
// speedup vs baseline: 3.2457x; 1.5180x over previous
#include <cuda_runtime.h>
#include <cuda_fp16.h>
#include <cuda_bf16.h>
#include <mma.h>
#include <cstdint>

using namespace nvcuda;

#define N_NODES 100000
#define N_EDGES 3200000
#define IN_F    256
#define OUT_F   128
#define NEG_SLOPE 0.2f

#define SCAN_BLK 1024
#define NB ((N_NODES + SCAN_BLK - 1) / SCAN_BLK)

// Scratch (static __device__ globals per allocation rules)
__device__ __half g_support_h[(size_t)N_NODES * OUT_F];   // 25.6 MB fp16 support
__device__ unsigned long long g_sorted[(size_t)N_EDGES];  // packed (col | val<<32)
__device__ int g_count[N_NODES];
__device__ int g_start[N_NODES + 1];
__device__ int g_cursor[N_NODES];
__device__ int g_bsum[NB];
__device__ int g_boff[NB];

// ---------------------------------------------------------------------------
// Kernel 1: fp16 tensor-core GEMM + LeakyReLU, fp16 epilogue.
//   C = F @ W^T  (fp16 inputs, fp32 accumulate)
// Software pipelined: global loads of K-step i+1 issue before MMAs of step i.
// ---------------------------------------------------------------------------
#define GBM 128
#define GKC 32
#define K_ITERS (IN_F / GKC)     // 8
#define A_LD 40                  // KC + 8 pad (fp16 elems)
#define C_LD 68                  // 64 + 4 pad (fp32 elems)

__global__ __launch_bounds__(256) void gemm_tc_kernel(
    const float* __restrict__ F, const float* __restrict__ W)
{
    __shared__ union {
        struct {
            __half Ah[GBM * A_LD];    // 10 KB
            __half Bh[OUT_F * A_LD];  // 10 KB
        } op;
        float Cs[GBM * C_LD];         // 34.8 KB (epilogue staging, half N)
    } sm;

    const int tid = threadIdx.x;
    const int wid = tid >> 5;
    const int wm  = wid & 3;        // warp row (4): rows wm*32..+32
    const int wn  = wid >> 2;       // warp col (2): cols wn*64..+64
    const int block_row = blockIdx.x * GBM;

    const int a_r  = tid >> 3;      // 0..31 (+t*32)
    const int a_c4 = tid & 7;

    wmma::fragment<wmma::accumulator, 16, 16, 16, float> acc[2][4];
#pragma unroll
    for (int i = 0; i < 2; ++i)
#pragma unroll
        for (int j = 0; j < 4; ++j) wmma::fill_fragment(acc[i][j], 0.f);

    float4 aReg[4], bReg[4];

    auto loadA = [&](int t, int k0) -> float4 {
        int r = a_r + t * 32;
        int grow = block_row + r;
        if (grow < N_NODES)
            return *reinterpret_cast<const float4*>(F + (size_t)grow * IN_F + k0 + a_c4 * 4);
        return make_float4(0.f, 0.f, 0.f, 0.f);
    };
    auto loadB = [&](int t, int k0) -> float4 {
        int n = a_r + t * 32;
        return *reinterpret_cast<const float4*>(W + (size_t)n * IN_F + k0 + a_c4 * 4);
    };

    // prologue: tile 0
#pragma unroll
    for (int t = 0; t < 4; ++t) { aReg[t] = loadA(t, 0); bReg[t] = loadB(t, 0); }

#pragma unroll 1
    for (int it = 0; it < K_ITERS; ++it) {
        // store current regs -> smem (fp16 convert), vectorized as half2
#pragma unroll
        for (int t = 0; t < 4; ++t) {
            int r = a_r + t * 32;
            __half2* ap = reinterpret_cast<__half2*>(&sm.op.Ah[r * A_LD + a_c4 * 4]);
            __half2* bp = reinterpret_cast<__half2*>(&sm.op.Bh[r * A_LD + a_c4 * 4]);
            ap[0] = __floats2half2_rn(aReg[t].x, aReg[t].y);
            ap[1] = __floats2half2_rn(aReg[t].z, aReg[t].w);
            bp[0] = __floats2half2_rn(bReg[t].x, bReg[t].y);
            bp[1] = __floats2half2_rn(bReg[t].z, bReg[t].w);
        }
        __syncthreads();

        // prefetch next tile into registers (overlaps with MMAs below)
        if (it + 1 < K_ITERS) {
            int k0 = (it + 1) * GKC;
#pragma unroll
            for (int t = 0; t < 4; ++t) { aReg[t] = loadA(t, k0); bReg[t] = loadB(t, k0); }
        }

        // MMAs on current smem stage
#pragma unroll
        for (int kk = 0; kk < GKC; kk += 16) {
            wmma::fragment<wmma::matrix_a, 16, 16, 16, __half, wmma::row_major> a_f[2];
#pragma unroll
            for (int i = 0; i < 2; ++i)
                wmma::load_matrix_sync(a_f[i], &sm.op.Ah[(wm * 32 + i * 16) * A_LD + kk], A_LD);
#pragma unroll
            for (int j = 0; j < 4; ++j) {
                wmma::fragment<wmma::matrix_b, 16, 16, 16, __half, wmma::col_major> b_f;
                wmma::load_matrix_sync(b_f, &sm.op.Bh[(wn * 64 + j * 16) * A_LD + kk], A_LD);
#pragma unroll
                for (int i = 0; i < 2; ++i)
                    wmma::mma_sync(acc[i][j], a_f[i], b_f, acc[i][j]);
            }
        }
        __syncthreads();
    }

    // Epilogue: two column-half passes through 128x64 fp32 staging.
#pragma unroll
    for (int p = 0; p < 2; ++p) {
        if (wn == p) {
#pragma unroll
            for (int i = 0; i < 2; ++i)
#pragma unroll
                for (int j = 0; j < 4; ++j)
                    wmma::store_matrix_sync(&sm.Cs[(wm * 32 + i * 16) * C_LD + j * 16],
                                            acc[i][j], C_LD, wmma::mem_row_major);
        }
        __syncthreads();
#pragma unroll
        for (int t = 0; t < 16; ++t) {
            int idx = tid + t * 256;        // 0..4095
            int r   = idx >> 5;             // 0..127
            int h2  = idx & 31;             // 0..31
            int grow = block_row + r;
            if (grow < N_NODES) {
                float x0 = sm.Cs[r * C_LD + h2 * 2 + 0];
                float x1 = sm.Cs[r * C_LD + h2 * 2 + 1];
                x0 = (x0 > 0.f) ? x0 : NEG_SLOPE * x0;
                x1 = (x1 > 0.f) ? x1 : NEG_SLOPE * x1;
                __half2* dst = reinterpret_cast<__half2*>(
                    g_support_h + (size_t)grow * OUT_F + p * 64);
                dst[h2] = __floats2half2_rn(x0, x1);
            }
        }
        __syncthreads();
    }
}

// ---------------------------------------------------------------------------
// Histogram of destination rows
// ---------------------------------------------------------------------------
__global__ __launch_bounds__(256) void hist_kernel(const int* __restrict__ rows)
{
    int e = blockIdx.x * blockDim.x + threadIdx.x;
    if (e < N_EDGES) atomicAdd(&g_count[rows[e]], 1);
}

// ---------------------------------------------------------------------------
// Parallel 3-phase scan
// ---------------------------------------------------------------------------
__global__ __launch_bounds__(SCAN_BLK) void scan_reduce_kernel()
{
    __shared__ int wsum[32];
    const int tid = threadIdx.x;
    const int i = blockIdx.x * SCAN_BLK + tid;
    int v = (i < N_NODES) ? g_count[i] : 0;
#pragma unroll
    for (int d = 16; d > 0; d >>= 1) v += __shfl_down_sync(0xffffffffu, v, d);
    if ((tid & 31) == 0) wsum[tid >> 5] = v;
    __syncthreads();
    if (tid < 32) {
        int s = wsum[tid];
#pragma unroll
        for (int d = 16; d > 0; d >>= 1) s += __shfl_down_sync(0xffffffffu, s, d);
        if (tid == 0) g_bsum[blockIdx.x] = s;
    }
}

__global__ __launch_bounds__(128) void scan_bsums_kernel()
{
    __shared__ int wsum[4];
    const int tid  = threadIdx.x;
    const int lane = tid & 31;
    const int wid  = tid >> 5;
    int v = (tid < NB) ? g_bsum[tid] : 0;
    int x = v;
#pragma unroll
    for (int d = 1; d < 32; d <<= 1) {
        int t = __shfl_up_sync(0xffffffffu, x, d);
        if (lane >= d) x += t;
    }
    if (lane == 31) wsum[wid] = x;
    __syncthreads();
    if (tid < 4) {
        int w = wsum[tid];
#pragma unroll
        for (int d = 1; d < 4; d <<= 1) {
            int t = __shfl_up_sync(0x0000000fu, w, d);
            if (tid >= d) w += t;
        }
        wsum[tid] = w;
    }
    __syncthreads();
    int excl = x - v + ((wid > 0) ? wsum[wid - 1] : 0);
    if (tid < NB) g_boff[tid] = excl;
    if (tid == 0) g_start[N_NODES] = N_EDGES;
}

__global__ __launch_bounds__(SCAN_BLK) void scan_final_kernel()
{
    __shared__ int wsum[32];
    const int tid  = threadIdx.x;
    const int lane = tid & 31;
    const int wid  = tid >> 5;
    const int i = blockIdx.x * SCAN_BLK + tid;
    int v = (i < N_NODES) ? g_count[i] : 0;
    int x = v;
#pragma unroll
    for (int d = 1; d < 32; d <<= 1) {
        int t = __shfl_up_sync(0xffffffffu, x, d);
        if (lane >= d) x += t;
    }
    if (lane == 31) wsum[wid] = x;
    __syncthreads();
    if (tid < 32) {
        int w = wsum[tid];
#pragma unroll
        for (int d = 1; d < 32; d <<= 1) {
            int t = __shfl_up_sync(0xffffffffu, w, d);
            if (tid >= d) w += t;
        }
        wsum[tid] = w;
    }
    __syncthreads();
    int excl = x - v + ((wid > 0) ? wsum[wid - 1] : 0) + g_boff[blockIdx.x];
    if (i < N_NODES) { g_start[i] = excl; g_cursor[i] = excl; }
}

// ---------------------------------------------------------------------------
// Bucket edges into row-sorted order
// ---------------------------------------------------------------------------
__global__ __launch_bounds__(256) void bucket_kernel(
    const float* __restrict__ vals,
    const int*   __restrict__ rows,
    const int*   __restrict__ cols)
{
    int e = blockIdx.x * blockDim.x + threadIdx.x;
    if (e >= N_EDGES) return;
    int r = rows[e];
    int pos = atomicAdd(&g_cursor[r], 1);
    unsigned long long rec = (unsigned int)cols[e]
                           | ((unsigned long long)__float_as_uint(vals[e]) << 32);
    g_sorted[pos] = rec;
}

// ---------------------------------------------------------------------------
// Row accumulation: one warp per row; fp16 gathers (256B/edge), unroll-4 MLP,
// fp32 register accumulators, single coalesced fp32 write.
// ---------------------------------------------------------------------------
__global__ __launch_bounds__(256) void row_accum_kernel(float* __restrict__ out)
{
    const int row  = blockIdx.x * 8 + (threadIdx.x >> 5);
    const int lane = threadIdx.x & 31;
    if (row >= N_NODES) return;

    const int beg = g_start[row];
    const int end = g_start[row + 1];

    const uint2* __restrict__ sup = reinterpret_cast<const uint2*>(g_support_h);

    float a0 = 0.f, a1 = 0.f, a2 = 0.f, a3 = 0.f;

    int i = beg;
    for (; i + 3 < end; i += 4) {
        unsigned long long e0 = g_sorted[i + 0];
        unsigned long long e1 = g_sorted[i + 1];
        unsigned long long e2 = g_sorted[i + 2];
        unsigned long long e3 = g_sorted[i + 3];
        int c0 = (int)(e0 & 0xffffffffu);
        int c1 = (int)(e1 & 0xffffffffu);
        int c2 = (int)(e2 & 0xffffffffu);
        int c3 = (int)(e3 & 0xffffffffu);
        float v0 = __uint_as_float((unsigned int)(e0 >> 32));
        float v1 = __uint_as_float((unsigned int)(e1 >> 32));
        float v2 = __uint_as_float((unsigned int)(e2 >> 32));
        float v3 = __uint_as_float((unsigned int)(e3 >> 32));
        uint2 p0 = sup[(size_t)c0 * 32 + lane];
        uint2 p1 = sup[(size_t)c1 * 32 + lane];
        uint2 p2 = sup[(size_t)c2 * 32 + lane];
        uint2 p3 = sup[(size_t)c3 * 32 + lane];
        float2 f;
        f = __half22float2(*reinterpret_cast<__half2*>(&p0.x)); a0 += v0 * f.x; a1 += v0 * f.y;
        f = __half22float2(*reinterpret_cast<__half2*>(&p0.y)); a2 += v0 * f.x; a3 += v0 * f.y;
        f = __half22float2(*reinterpret_cast<__half2*>(&p1.x)); a0 += v1 * f.x; a1 += v1 * f.y;
        f = __half22float2(*reinterpret_cast<__half2*>(&p1.y)); a2 += v1 * f.x; a3 += v1 * f.y;
        f = __half22float2(*reinterpret_cast<__half2*>(&p2.x)); a0 += v2 * f.x; a1 += v2 * f.y;
        f = __half22float2(*reinterpret_cast<__half2*>(&p2.y)); a2 += v2 * f.x; a3 += v2 * f.y;
        f = __half22float2(*reinterpret_cast<__half2*>(&p3.x)); a0 += v3 * f.x; a1 += v3 * f.y;
        f = __half22float2(*reinterpret_cast<__half2*>(&p3.y)); a2 += v3 * f.x; a3 += v3 * f.y;
    }
    for (; i < end; ++i) {
        unsigned long long e0 = g_sorted[i];
        int   c0 = (int)(e0 & 0xffffffffu);
        float v0 = __uint_as_float((unsigned int)(e0 >> 32));
        uint2 p0 = sup[(size_t)c0 * 32 + lane];
        float2 f;
        f = __half22float2(*reinterpret_cast<__half2*>(&p0.x)); a0 += v0 * f.x; a1 += v0 * f.y;
        f = __half22float2(*reinterpret_cast<__half2*>(&p0.y)); a2 += v0 * f.x; a3 += v0 * f.y;
    }

    reinterpret_cast<float4*>(out)[(size_t)row * 32 + lane] =
        make_float4(a0, a1, a2, a3);
}

// ---------------------------------------------------------------------------
// launch — GEMM runs concurrently with the edge-sort pipeline on a second
// stream (data-independent), fork/join via events (graph-capturable).
// ---------------------------------------------------------------------------
extern "C" void kernel_launch(void* const* d_in, const int* in_sizes, int n_in,
                              void* d_out, int out_size)
{
    const float* features = (const float*)d_in[0];
    const float* weight   = (const float*)d_in[1];
    const float* evals    = (const float*)d_in[2];
    const int*   erows    = (const int*)d_in[3];
    const int*   ecols    = (const int*)d_in[4];
    float*       out      = (float*)d_out;

    static cudaStream_t s2 = nullptr;
    static cudaEvent_t evFork = nullptr, evJoin = nullptr;
    if (s2 == nullptr) {
        cudaStreamCreateWithFlags(&s2, cudaStreamNonBlocking);
        cudaEventCreateWithFlags(&evFork, cudaEventDisableTiming);
        cudaEventCreateWithFlags(&evJoin, cudaEventDisableTiming);
    }

    // fork
    cudaEventRecord(evFork, 0);
    cudaStreamWaitEvent(s2, evFork, 0);

    // Stream 0: tensor-core GEMM + lrelu -> g_support_h (fp16)
    gemm_tc_kernel<<<(N_NODES + GBM - 1) / GBM, 256, 0, 0>>>(features, weight);

    // Stream s2: counting sort of edges by destination row
    void* count_ptr = nullptr;
    cudaGetSymbolAddress(&count_ptr, g_count);
    cudaMemsetAsync(count_ptr, 0, sizeof(int) * N_NODES, s2);
    hist_kernel<<<(N_EDGES + 255) / 256, 256, 0, s2>>>(erows);
    scan_reduce_kernel<<<NB, SCAN_BLK, 0, s2>>>();
    scan_bsums_kernel<<<1, 128, 0, s2>>>();
    scan_final_kernel<<<NB, SCAN_BLK, 0, s2>>>();
    bucket_kernel<<<(N_EDGES + 255) / 256, 256, 0, s2>>>(evals, erows, ecols);

    // join
    cudaEventRecord(evJoin, s2);
    cudaStreamWaitEvent(0, evJoin, 0);

    // Owner-computes reduction: one warp per row, no atomics
    row_accum_kernel<<<(N_NODES + 7) / 8, 256, 0, 0>>>(out);
}